// round 1
// baseline (speedup 1.0000x reference)
#include <cuda_runtime.h>

#define NN 20000
#define NE 320000
#define LDIM 128
#define TILE 64
#define NT 256
#define NLAYERS 5

// -------- scratch (static device allocations; no runtime alloc) --------
__device__ float g_h[NN * LDIM];     // node features
__device__ float g_P[NN * LDIM];     // h @ W1a  (dst-side precontraction)
__device__ float g_Q[NN * LDIM];     // h @ W1b  (src-side precontraction)
__device__ float g_agg[NN * LDIM];   // segment sum accumulator
__device__ float g_e[NE * LDIM];     // encoded edge features (constant over layers)

// -------- helpers --------
__device__ __forceinline__ void cp_f4(float* dst, const float* __restrict__ src,
                                      int n, int tid) {
    for (int i = tid * 4; i < n; i += NT * 4)
        *(float4*)(dst + i) = *(const float4*)(src + i);
}

// load a 64 x 128 row tile from a [nrows,128] matrix, clamping out-of-range rows
__device__ __forceinline__ void load_tile_rows(float* As, const float* __restrict__ src,
                                               int r0, int nrows, int tid) {
    for (int i = tid * 4; i < TILE * LDIM; i += NT * 4) {
        int r = i >> 7;
        int k = i & (LDIM - 1);
        int gr = r0 + r;
        if (gr >= nrows) gr = nrows - 1;
        *(float4*)(As + i) = *(const float4*)(src + (size_t)gr * LDIM + k);
    }
}

__device__ __forceinline__ void red_add_v4(float* addr, float4 v) {
    asm volatile("red.global.add.v4.f32 [%0], {%1,%2,%3,%4};"
                 :: "l"(addr), "f"(v.x), "f"(v.y), "f"(v.z), "f"(v.w)
                 : "memory");
}

__device__ __forceinline__ void prelu4(float4& v, float a) {
    v.x = v.x > 0.f ? v.x : a * v.x;
    v.y = v.y > 0.f ? v.y : a * v.y;
    v.z = v.z > 0.f ? v.z : a * v.z;
    v.w = v.w > 0.f ? v.w : a * v.w;
}

// acc[8] (8 rows x 4 cols per thread). As: [TILE][ASTRIDE]. Ws: [K][128].
template<int K, int ASTRIDE>
__device__ __forceinline__ void gemm_acc(const float* __restrict__ As,
                                         const float* __restrict__ Ws,
                                         int row_base, int c0, float4 acc[8]) {
#pragma unroll 4
    for (int k = 0; k < K; ++k) {
        float4 w = *(const float4*)(Ws + k * LDIM + c0);
#pragma unroll
        for (int r = 0; r < 8; ++r) {
            float a = As[(row_base + r) * ASTRIDE + k];
            acc[r].x = fmaf(a, w.x, acc[r].x);
            acc[r].y = fmaf(a, w.y, acc[r].y);
            acc[r].z = fmaf(a, w.z, acc[r].z);
            acc[r].w = fmaf(a, w.w, acc[r].w);
        }
    }
}

// ============================ encoder (node / edge) ============================
template<int K1>
__global__ __launch_bounds__(NT, 2)
void encoder_kernel(const float* __restrict__ in,
                    const float* __restrict__ w1, const float* __restrict__ b1,
                    const float* __restrict__ aslope,
                    const float* __restrict__ w2, const float* __restrict__ b2,
                    float* __restrict__ out, int nrows) {
    extern __shared__ float sm[];
    float* Ws  = sm;                       // 128*128
    float* As  = sm + LDIM * LDIM;         // 64*128 (U buffer)
    float* Ain = As + TILE * LDIM;         // 64*K1
    int tid = threadIdx.x;
    int ty = tid >> 5, tx = tid & 31;
    int row_base = ty * 8, c0 = tx * 4;
    int r0 = blockIdx.x * TILE;

    for (int i = tid; i < TILE * K1; i += NT) {
        int r = i / K1, k = i - r * K1;
        int gr = r0 + r; if (gr >= nrows) gr = nrows - 1;
        Ain[i] = in[(size_t)gr * K1 + k];
    }
    cp_f4(Ws, w1, K1 * LDIM, tid);
    __syncthreads();

    float4 b1v = *(const float4*)(b1 + c0);
    float4 acc[8];
#pragma unroll
    for (int r = 0; r < 8; ++r) acc[r] = b1v;
    gemm_acc<K1, K1>(Ain, Ws, row_base, c0, acc);

    float al = *aslope;
#pragma unroll
    for (int r = 0; r < 8; ++r) prelu4(acc[r], al);

    // U -> As (As unused during GEMM1), reload Ws with w2
#pragma unroll
    for (int r = 0; r < 8; ++r)
        *(float4*)(As + (row_base + r) * LDIM + c0) = acc[r];
    __syncthreads();                 // all done reading Ws(w1)
    cp_f4(Ws, w2, LDIM * LDIM, tid);
    __syncthreads();

    float4 b2v = *(const float4*)(b2 + c0);
#pragma unroll
    for (int r = 0; r < 8; ++r) acc[r] = b2v;
    gemm_acc<LDIM, LDIM>(As, Ws, row_base, c0, acc);

#pragma unroll
    for (int r = 0; r < 8; ++r) {
        int gr = r0 + row_base + r;
        if (gr < nrows) *(float4*)(out + (size_t)gr * LDIM + c0) = acc[r];
    }
}

// ============================ per-layer: P/Q + zero agg ============================
__global__ __launch_bounds__(NT, 2)
void pq_kernel(const float* __restrict__ wl /* le_w1 layer base [384,128] */) {
    extern __shared__ float sm[];
    float* Ws = sm;
    float* As = sm + LDIM * LDIM;
    int tid = threadIdx.x;
    int ty = tid >> 5, tx = tid & 31;
    int row_base = ty * 8, c0 = tx * 4;
    int r0 = blockIdx.x * TILE;

    load_tile_rows(As, g_h, r0, NN, tid);
    cp_f4(Ws, wl, LDIM * LDIM, tid);          // W1a (rows 0..127, dst side)
    __syncthreads();

    float4 acc[8];
    float4 z = make_float4(0.f, 0.f, 0.f, 0.f);
#pragma unroll
    for (int r = 0; r < 8; ++r) acc[r] = z;
    gemm_acc<LDIM, LDIM>(As, Ws, row_base, c0, acc);
#pragma unroll
    for (int r = 0; r < 8; ++r) {
        int gr = r0 + row_base + r;
        if (gr < NN) {
            *(float4*)(g_P + (size_t)gr * LDIM + c0) = acc[r];
            *(float4*)(g_agg + (size_t)gr * LDIM + c0) = z;   // zero agg for this layer
        }
    }
    __syncthreads();
    cp_f4(Ws, wl + LDIM * LDIM, LDIM * LDIM, tid);  // W1b (rows 128..255, src side)
    __syncthreads();
#pragma unroll
    for (int r = 0; r < 8; ++r) acc[r] = z;
    gemm_acc<LDIM, LDIM>(As, Ws, row_base, c0, acc);
#pragma unroll
    for (int r = 0; r < 8; ++r) {
        int gr = r0 + row_base + r;
        if (gr < NN) *(float4*)(g_Q + (size_t)gr * LDIM + c0) = acc[r];
    }
}

// ============================ per-layer: edge messages + scatter ============================
__global__ __launch_bounds__(NT, 2)
void edge_kernel(const int* __restrict__ eidx,
                 const float* __restrict__ wl,    // le_w1 layer base [384,128]
                 const float* __restrict__ b1, const float* __restrict__ aslope,
                 const float* __restrict__ w2, const float* __restrict__ b2) {
    extern __shared__ float sm[];
    float* Ws = sm;
    float* As = sm + LDIM * LDIM;
    int* sdst = (int*)(As + TILE * LDIM);
    int* ssrc = sdst + TILE;
    int tid = threadIdx.x;
    int ty = tid >> 5, tx = tid & 31;
    int row_base = ty * 8, c0 = tx * 4;
    size_t e0 = (size_t)blockIdx.x * TILE;

    cp_f4(As, g_e + e0 * LDIM, TILE * LDIM, tid);      // e tile (contiguous rows)
    cp_f4(Ws, wl + 256 * LDIM, LDIM * LDIM, tid);      // W1c (rows 256..383, e side)
    if (tid < TILE) {
        ssrc[tid] = eidx[e0 + tid];        // edge_index[0] = src (x_j)
        sdst[tid] = eidx[NE + e0 + tid];   // edge_index[1] = dst (x_i / agg index)
    }
    __syncthreads();

    float4 b1v = *(const float4*)(b1 + c0);
    float4 acc[8];
#pragma unroll
    for (int r = 0; r < 8; ++r) {
        int d = sdst[row_base + r];
        int s = ssrc[row_base + r];
        float4 pv = *(const float4*)(g_P + (size_t)d * LDIM + c0);
        float4 qv = *(const float4*)(g_Q + (size_t)s * LDIM + c0);
        acc[r].x = b1v.x + pv.x + qv.x;
        acc[r].y = b1v.y + pv.y + qv.y;
        acc[r].z = b1v.z + pv.z + qv.z;
        acc[r].w = b1v.w + pv.w + qv.w;
    }
    gemm_acc<LDIM, LDIM>(As, Ws, row_base, c0, acc);

    float al = *aslope;
#pragma unroll
    for (int r = 0; r < 8; ++r) prelu4(acc[r], al);

    __syncthreads();              // all threads done reading e tile + W1c
#pragma unroll
    for (int r = 0; r < 8; ++r)
        *(float4*)(As + (row_base + r) * LDIM + c0) = acc[r];   // U
    cp_f4(Ws, w2, LDIM * LDIM, tid);
    __syncthreads();

    float4 b2v = *(const float4*)(b2 + c0);
#pragma unroll
    for (int r = 0; r < 8; ++r) acc[r] = b2v;
    gemm_acc<LDIM, LDIM>(As, Ws, row_base, c0, acc);

    // scatter-add m into agg[dst] (m never materialized)
#pragma unroll
    for (int r = 0; r < 8; ++r) {
        int d = sdst[row_base + r];
        red_add_v4(g_agg + (size_t)d * LDIM + c0, acc[r]);
    }
}

// ============================ per-layer: node update ============================
__global__ __launch_bounds__(NT, 2)
void node_kernel(const float* __restrict__ wn1,  // ln_w1 layer base [256,128]
                 const float* __restrict__ b1, const float* __restrict__ aslope,
                 const float* __restrict__ w2, const float* __restrict__ b2) {
    extern __shared__ float sm[];
    float* Ws = sm;
    float* As = sm + LDIM * LDIM;
    int tid = threadIdx.x;
    int ty = tid >> 5, tx = tid & 31;
    int row_base = ty * 8, c0 = tx * 4;
    int r0 = blockIdx.x * TILE;

    load_tile_rows(As, g_h, r0, NN, tid);
    cp_f4(Ws, wn1, LDIM * LDIM, tid);          // rows 0..127 (h side)
    __syncthreads();

    float4 b1v = *(const float4*)(b1 + c0);
    float4 acc[8];
#pragma unroll
    for (int r = 0; r < 8; ++r) acc[r] = b1v;
    gemm_acc<LDIM, LDIM>(As, Ws, row_base, c0, acc);

    __syncthreads();
    load_tile_rows(As, g_agg, r0, NN, tid);
    cp_f4(Ws, wn1 + LDIM * LDIM, LDIM * LDIM, tid);   // rows 128..255 (agg side)
    __syncthreads();
    gemm_acc<LDIM, LDIM>(As, Ws, row_base, c0, acc);  // accumulate

    float al = *aslope;
#pragma unroll
    for (int r = 0; r < 8; ++r) prelu4(acc[r], al);

    __syncthreads();
#pragma unroll
    for (int r = 0; r < 8; ++r)
        *(float4*)(As + (row_base + r) * LDIM + c0) = acc[r];   // U
    cp_f4(Ws, w2, LDIM * LDIM, tid);
    __syncthreads();

    float4 b2v = *(const float4*)(b2 + c0);
#pragma unroll
    for (int r = 0; r < 8; ++r) acc[r] = b2v;
    gemm_acc<LDIM, LDIM>(As, Ws, row_base, c0, acc);

#pragma unroll
    for (int r = 0; r < 8; ++r) {
        int gr = r0 + row_base + r;
        if (gr < NN) {
            float4 hv = *(const float4*)(g_h + (size_t)gr * LDIM + c0);
            hv.x += acc[r].x; hv.y += acc[r].y; hv.z += acc[r].z; hv.w += acc[r].w;
            *(float4*)(g_h + (size_t)gr * LDIM + c0) = hv;      // h = h + upd
        }
    }
}

// ============================ decoder ============================
__global__ __launch_bounds__(NT, 2)
void dec_kernel(const float* __restrict__ w1, const float* __restrict__ b1,
                const float* __restrict__ aslope,
                const float* __restrict__ w2, const float* __restrict__ b2,
                float* __restrict__ out) {
    extern __shared__ float sm[];
    float* Ws = sm;
    float* As = sm + LDIM * LDIM;
    int tid = threadIdx.x;
    int ty = tid >> 5, tx = tid & 31;
    int row_base = ty * 8, c0 = tx * 4;
    int r0 = blockIdx.x * TILE;

    load_tile_rows(As, g_h, r0, NN, tid);
    cp_f4(Ws, w1, LDIM * LDIM, tid);
    __syncthreads();

    float4 b1v = *(const float4*)(b1 + c0);
    float4 acc[8];
#pragma unroll
    for (int r = 0; r < 8; ++r) acc[r] = b1v;
    gemm_acc<LDIM, LDIM>(As, Ws, row_base, c0, acc);

    float al = *aslope;
#pragma unroll
    for (int r = 0; r < 8; ++r) prelu4(acc[r], al);

    __syncthreads();
#pragma unroll
    for (int r = 0; r < 8; ++r)
        *(float4*)(As + (row_base + r) * LDIM + c0) = acc[r];   // U
    __syncthreads();

    if (tid < TILE * 3) {
        int r = tid / 3, c = tid - r * 3;
        int gr = r0 + r;
        if (gr < NN) {
            float s = b2[c];
#pragma unroll 8
            for (int k = 0; k < LDIM; ++k)
                s = fmaf(As[r * LDIM + k], w2[k * 3 + c], s);
            out[(size_t)gr * 3 + c] = s;
        }
    }
}

// ============================ host ============================
extern "C" void kernel_launch(void* const* d_in, const int* in_sizes, int n_in,
                              void* d_out, int out_size) {
    const float* x          = (const float*)d_in[0];
    const float* edge_attr  = (const float*)d_in[1];
    const int*   edge_index = (const int*)  d_in[2];
    const float* ne_w1 = (const float*)d_in[3];
    const float* ne_b1 = (const float*)d_in[4];
    const float* ne_a  = (const float*)d_in[5];
    const float* ne_w2 = (const float*)d_in[6];
    const float* ne_b2 = (const float*)d_in[7];
    const float* ee_w1 = (const float*)d_in[8];
    const float* ee_b1 = (const float*)d_in[9];
    const float* ee_a  = (const float*)d_in[10];
    const float* ee_w2 = (const float*)d_in[11];
    const float* ee_b2 = (const float*)d_in[12];
    const float* le_w1 = (const float*)d_in[13];
    const float* le_b1 = (const float*)d_in[14];
    const float* le_a  = (const float*)d_in[15];
    const float* le_w2 = (const float*)d_in[16];
    const float* le_b2 = (const float*)d_in[17];
    const float* ln_w1 = (const float*)d_in[18];
    const float* ln_b1 = (const float*)d_in[19];
    const float* ln_a  = (const float*)d_in[20];
    const float* ln_w2 = (const float*)d_in[21];
    const float* ln_b2 = (const float*)d_in[22];
    const float* de_w1 = (const float*)d_in[23];
    const float* de_b1 = (const float*)d_in[24];
    const float* de_a  = (const float*)d_in[25];
    const float* de_w2 = (const float*)d_in[26];
    const float* de_b2 = (const float*)d_in[27];
    float* out = (float*)d_out;

    float *p_h = nullptr, *p_e = nullptr;
    cudaGetSymbolAddress((void**)&p_h, g_h);
    cudaGetSymbolAddress((void**)&p_e, g_e);

    const int SMEM_GEMM  = (LDIM * LDIM + TILE * LDIM) * 4;      // 96 KB
    const int SMEM_EDGE  = SMEM_GEMM + 2 * TILE * 4;             // + index staging
    const int SMEM_ENC30 = SMEM_GEMM + TILE * 30 * 4;
    const int SMEM_ENC4  = SMEM_GEMM + TILE * 4 * 4;

    cudaFuncSetAttribute(encoder_kernel<30>, cudaFuncAttributeMaxDynamicSharedMemorySize, SMEM_ENC30);
    cudaFuncSetAttribute(encoder_kernel<4>,  cudaFuncAttributeMaxDynamicSharedMemorySize, SMEM_ENC4);
    cudaFuncSetAttribute(pq_kernel,   cudaFuncAttributeMaxDynamicSharedMemorySize, SMEM_GEMM);
    cudaFuncSetAttribute(edge_kernel, cudaFuncAttributeMaxDynamicSharedMemorySize, SMEM_EDGE);
    cudaFuncSetAttribute(node_kernel, cudaFuncAttributeMaxDynamicSharedMemorySize, SMEM_GEMM);
    cudaFuncSetAttribute(dec_kernel,  cudaFuncAttributeMaxDynamicSharedMemorySize, SMEM_GEMM);

    const int nb_n = (NN + TILE - 1) / TILE;   // 313
    const int nb_e = NE / TILE;                // 5000

    encoder_kernel<30><<<nb_n, NT, SMEM_ENC30>>>(x, ne_w1, ne_b1, ne_a, ne_w2, ne_b2, p_h, NN);
    encoder_kernel<4> <<<nb_e, NT, SMEM_ENC4 >>>(edge_attr, ee_w1, ee_b1, ee_a, ee_w2, ee_b2, p_e, NE);

    for (int l = 0; l < NLAYERS; ++l) {
        const float* wl = le_w1 + (size_t)l * 384 * LDIM;
        pq_kernel<<<nb_n, NT, SMEM_GEMM>>>(wl);
        edge_kernel<<<nb_e, NT, SMEM_EDGE>>>(edge_index, wl,
                                             le_b1 + l * LDIM, le_a + l,
                                             le_w2 + (size_t)l * LDIM * LDIM,
                                             le_b2 + l * LDIM);
        node_kernel<<<nb_n, NT, SMEM_GEMM>>>(ln_w1 + (size_t)l * 256 * LDIM,
                                             ln_b1 + l * LDIM, ln_a + l,
                                             ln_w2 + (size_t)l * LDIM * LDIM,
                                             ln_b2 + l * LDIM);
    }
    dec_kernel<<<nb_n, NT, SMEM_GEMM>>>(de_w1, de_b1, de_a, de_w2, de_b2, out);
}